// round 15
// baseline (speedup 1.0000x reference)
#include <cuda_runtime.h>
#include <cuda_bf16.h>
#include <stdint.h>
#include <math.h>

#define S_TOK 1024
#define CDIM  512
#define NTOK  16384   // B * S_TOK

// ---- scratch (static device globals; no runtime allocation) ----
__device__ __nv_bfloat16 g_xn_h  [NTOK * CDIM];
__device__ __nv_bfloat16 g_attn_h[NTOK * CDIM];
__device__ __nv_bfloat16 g_wt    [12 * CDIM * CDIM];  // [z][n][k] bf16
__device__ __nv_bfloat16 g_qh[NTOK * CDIM];
__device__ __nv_bfloat16 g_kh[NTOK * CDIM];
__device__ __nv_bfloat16 g_vh[NTOK * CDIM];
__device__ float g_part[16 * 8 * 32 * 2];   // [b][chunk][g][{sum,sumsq}]

__device__ __forceinline__ unsigned pack_bf2(float a, float b) {
    __nv_bfloat162 h = __floats2bfloat162_rn(a, b);
    return *(unsigned*)&h;
}

// ============================================================
// GroupNorm stats
// ============================================================
__global__ void gn_stats(const float* __restrict__ x) {
    int b = blockIdx.x >> 3, chunk = blockIdx.x & 7;
    int tid = threadIdx.x;
    int cpos = tid & 127;
    int trow = tid >> 7;
    const float* xb = x + ((size_t)b * S_TOK + chunk * 128 + trow) * CDIM + cpos * 4;

    float s = 0.f, q = 0.f;
#pragma unroll 8
    for (int i = 0; i < 64; i++) {
        float4 v = *(const float4*)(xb + (size_t)(2 * i) * CDIM);
        s += v.x + v.y + v.z + v.w;
        q += v.x * v.x + v.y * v.y + v.z * v.z + v.w * v.w;
    }
    __shared__ float red[256], red2[256];
    red[tid] = s; red2[tid] = q;
    __syncthreads();
    if (tid < 32) {
        float S = 0.f, Q = 0.f;
#pragma unroll
        for (int j = 0; j < 4; j++) {
            S += red[4 * tid + j] + red[128 + 4 * tid + j];
            Q += red2[4 * tid + j] + red2[128 + 4 * tid + j];
        }
        float* p = g_part + (((size_t)b * 8 + chunk) * 32 + tid) * 2;
        p[0] = S; p[1] = Q;
    }
}

// ============================================================
// GroupNorm apply
// ============================================================
__global__ void gn_apply(const float* __restrict__ x,
                         const float* __restrict__ gamma,
                         const float* __restrict__ beta,
                         __nv_bfloat16* __restrict__ xn) {
    int b = blockIdx.x >> 5, chunk = blockIdx.x & 31;
    int tid = threadIdx.x;

    __shared__ float mean_s[32], inv_s[32];
    __shared__ float scale_s[CDIM], shift_s[CDIM];

    if (tid < 32) {
        float S = 0.f, Q = 0.f;
#pragma unroll
        for (int c = 0; c < 8; c++) {
            const float* p = g_part + (((size_t)b * 8 + c) * 32 + tid) * 2;
            S += p[0]; Q += p[1];
        }
        float mean = S * (1.f / 16384.f);
        float var  = Q * (1.f / 16384.f) - mean * mean;
        mean_s[tid] = mean;
        inv_s[tid]  = rsqrtf(var + 1e-5f);
    }
    __syncthreads();
#pragma unroll
    for (int c = tid; c < CDIM; c += 256) {
        int g = c >> 4;
        float ga = gamma[c], be = beta[c];
        float sc = inv_s[g] * ga;
        scale_s[c] = sc;
        shift_s[c] = be - mean_s[g] * sc;
    }
    __syncthreads();

    int cpos = tid & 127, trow = tid >> 7;
    size_t base = ((size_t)b * S_TOK + chunk * 32 + trow) * CDIM + cpos * 4;
    const float* xb = x + base;
    __nv_bfloat16* xo = g_xn_h + base;
    (void)xn;
    float4 sc4 = *(const float4*)(scale_s + cpos * 4);
    float4 sh4 = *(const float4*)(shift_s + cpos * 4);
#pragma unroll
    for (int i = 0; i < 16; i++) {
        float4 v = *(const float4*)(xb + (size_t)(2 * i) * CDIM);
        float o0 = fmaf(v.x, sc4.x, sh4.x);
        float o1 = fmaf(v.y, sc4.y, sh4.y);
        float o2 = fmaf(v.z, sc4.z, sh4.z);
        float o3 = fmaf(v.w, sc4.w, sh4.w);
        uint2 pk = make_uint2(pack_bf2(o0, o1), pack_bf2(o2, o3));
        *(uint2*)(xo + (size_t)(2 * i) * CDIM) = pk;
    }
}

// ============================================================
// Weight transpose + convert: out[z][n][k] = bf16(src_z[k][n])
// ============================================================
__global__ void wt_kernel(const float* __restrict__ wq, const float* __restrict__ wk,
                          const float* __restrict__ wv, const float* __restrict__ cw,
                          __nv_bfloat16* __restrict__ out) {
    __shared__ float tile[32][33];
    int z = blockIdx.z;
    const float* src = (z == 0) ? wq : (z == 1) ? wk : (z == 2) ? wv
                       : cw + (size_t)(z - 3) * CDIM * CDIM;
    __nv_bfloat16* dst = out + (size_t)z * CDIM * CDIM;
    int k0 = blockIdx.y * 32, n0 = blockIdx.x * 32;
    int tx = threadIdx.x, ty = threadIdx.y;
#pragma unroll
    for (int i = 0; i < 32; i += 8)
        tile[ty + i][tx] = src[(size_t)(k0 + ty + i) * CDIM + n0 + tx];
    __syncthreads();
#pragma unroll
    for (int i = 0; i < 32; i += 8)
        dst[(size_t)(n0 + ty + i) * CDIM + k0 + tx] = __float2bfloat16(tile[tx][ty + i]);
}

// ============================================================
// mma / ldmatrix / cp.async helpers
// ============================================================
#define MMA_BF16(d, a, b0, b1)                                              \
    asm volatile(                                                           \
        "mma.sync.aligned.m16n8k16.row.col.f32.bf16.bf16.f32 "              \
        "{%0,%1,%2,%3}, {%4,%5,%6,%7}, {%8,%9}, {%0,%1,%2,%3};\n"           \
        : "+f"(d[0]), "+f"(d[1]), "+f"(d[2]), "+f"(d[3])                    \
        : "r"(a[0]), "r"(a[1]), "r"(a[2]), "r"(a[3]), "r"(b0), "r"(b1))

#define LDSM4(r, addr)                                                      \
    asm volatile("ldmatrix.sync.aligned.m8n8.x4.shared.b16 {%0,%1,%2,%3}, [%4];\n" \
                 : "=r"(r[0]), "=r"(r[1]), "=r"(r[2]), "=r"(r[3]) : "r"(addr))

#define LDSM4T(r, addr)                                                     \
    asm volatile("ldmatrix.sync.aligned.m8n8.x4.trans.shared.b16 {%0,%1,%2,%3}, [%4];\n" \
                 : "=r"(r[0]), "=r"(r[1]), "=r"(r[2]), "=r"(r[3]) : "r"(addr))

#define CP_ASYNC16(daddr, gptr, sz)                                         \
    asm volatile("cp.async.cg.shared.global [%0], [%1], 16, %2;\n"          \
                 :: "r"(daddr), "l"(gptr), "r"(sz))
#define CP_COMMIT() asm volatile("cp.async.commit_group;\n")

#define MULBF2(dst, a, b)                                                   \
    asm volatile("mul.rn.bf16x2 %0, %1, %2;\n" : "=r"(dst) : "r"(a), "r"(b))

// ============================================================
// BF16 GEMM (R7 body): 8 warps, 64x32 warp tiles, CTA 128x128,
// BK=32, 3-stage cp.async ring, 80B stride.
// blockIdx.z selects weight + output when nz>1 (QKV fusion).
// ============================================================
#define STG_BYTES 20480   // per stage: A 128*80 + B 128*80

__global__ __launch_bounds__(256)
void gemm_bf16(const __nv_bfloat16* __restrict__ A,
               const __nv_bfloat16* __restrict__ Wt,
               void* __restrict__ o0, void* __restrict__ o1, void* __restrict__ o2,
               int ntaps, int obf,
               const float* __restrict__ bias,
               const float* __restrict__ residual, int epi) {
    extern __shared__ char smem[];

    int tid = threadIdx.x, warp = tid >> 5, lane = tid & 31;
    int g = lane >> 2, t = lane & 3;
    int m0 = blockIdx.y * 128, n0 = blockIdx.x * 128;
    int wm = (warp >> 2) * 64, wn = (warp & 3) * 32;

    const __nv_bfloat16* W0 = Wt + (size_t)blockIdx.z * CDIM * CDIM;
    void* Cout = (blockIdx.z == 0) ? o0 : (blockIdx.z == 1) ? o1 : o2;

    int lrow = tid >> 2, lchunk = tid & 3;
    int bidx[2], hh0[2], ww0[2];
#pragma unroll
    for (int p = 0; p < 2; p++) {
        int mg = m0 + lrow + 64 * p;
        bidx[p] = mg >> 10;
        int s = mg & 1023;
        hh0[p] = s >> 5; ww0[p] = s & 31;
    }

    float acc[4][4][4];
#pragma unroll
    for (int mi = 0; mi < 4; mi++)
#pragma unroll
        for (int nj = 0; nj < 4; nj++)
#pragma unroll
            for (int c = 0; c < 4; c++) acc[mi][nj][c] = 0.f;

    const int NIT = ntaps * 16;

#define LOAD_TILE(IT, ST)                                                   \
    {                                                                       \
        int tap = (IT) >> 4;                                                \
        int k0 = ((IT) & 15) << 5;                                          \
        int dh = 0, dw = 0;                                                 \
        if (ntaps > 1) { int r3 = tap / 3; dh = r3 - 1; dw = tap - r3 * 3 - 1; } \
        char* as = smem + (ST) * STG_BYTES;                                 \
        char* bs = as + 10240;                                              \
        _Pragma("unroll")                                                   \
        for (int p = 0; p < 2; p++) {                                       \
            int hh = hh0[p] + dh, ww = ww0[p] + dw;                         \
            bool valid = ((unsigned)hh < 32u) && ((unsigned)ww < 32u);      \
            const __nv_bfloat16* gp = A + (size_t)((bidx[p] << 10) + (hh << 5) + ww) * CDIM + k0 + lchunk * 8; \
            unsigned da = (unsigned)__cvta_generic_to_shared(as + (lrow + 64 * p) * 80 + lchunk * 16); \
            CP_ASYNC16(da, gp, valid ? 16 : 0);                             \
        }                                                                   \
        const __nv_bfloat16* wb = W0 + (size_t)tap * CDIM * CDIM + (size_t)n0 * CDIM + k0; \
        _Pragma("unroll")                                                   \
        for (int p = 0; p < 2; p++) {                                       \
            const __nv_bfloat16* gp = wb + (size_t)(lrow + 64 * p) * CDIM + lchunk * 8; \
            unsigned da = (unsigned)__cvta_generic_to_shared(bs + (lrow + 64 * p) * 80 + lchunk * 16); \
            CP_ASYNC16(da, gp, 16);                                         \
        }                                                                   \
        CP_COMMIT();                                                        \
    }

    LOAD_TILE(0, 0);
    LOAD_TILE(1, 1);

    int arow_f = wm + (lane & 15);
    int akoff  = (lane >> 4) * 8;
    int brow_f = wn + (lane & 7) + ((lane >> 4) << 3);
    int bkoff  = ((lane >> 3) & 1) * 8;

    int st = 0;
    for (int it = 0; it < NIT; it++) {
        if (it + 1 < NIT) asm volatile("cp.async.wait_group 1;");
        else              asm volatile("cp.async.wait_group 0;");
        __syncthreads();
        if (it + 2 < NIT) {
            int wst = st + 2; if (wst >= 3) wst -= 3;
            LOAD_TILE(it + 2, wst);
        }
        char* as = smem + st * STG_BYTES;
        char* bs = as + 10240;
        unsigned abase = (unsigned)__cvta_generic_to_shared(as);
        unsigned bbase = (unsigned)__cvta_generic_to_shared(bs);

#pragma unroll
        for (int ks = 0; ks < 2; ks++) {
            unsigned bfr[2][4];
#pragma unroll
            for (int njp = 0; njp < 2; njp++) {
                unsigned addr = bbase + ((brow_f + njp * 16) * 40 + ks * 16 + bkoff) * 2;
                LDSM4(bfr[njp], addr);
            }
#pragma unroll
            for (int mi = 0; mi < 4; mi++) {
                unsigned af[4];
                unsigned addr = abase + ((arow_f + mi * 16) * 40 + ks * 16 + akoff) * 2;
                LDSM4(af, addr);
                MMA_BF16(acc[mi][0], af, bfr[0][0], bfr[0][1]);
                MMA_BF16(acc[mi][1], af, bfr[0][2], bfr[0][3]);
                MMA_BF16(acc[mi][2], af, bfr[1][0], bfr[1][1]);
                MMA_BF16(acc[mi][3], af, bfr[1][2], bfr[1][3]);
            }
        }
        st++; if (st == 3) st = 0;
    }

    // epilogue
#pragma unroll
    for (int mi = 0; mi < 4; mi++) {
        int r0 = m0 + wm + mi * 16 + g;
        int r1 = r0 + 8;
#pragma unroll
        for (int nj = 0; nj < 4; nj++) {
            int col = n0 + wn + nj * 8 + 2 * t;
            float2 v01 = make_float2(acc[mi][nj][0], acc[mi][nj][1]);
            float2 v23 = make_float2(acc[mi][nj][2], acc[mi][nj][3]);
            if (obf) {
                __nv_bfloat16* C = (__nv_bfloat16*)Cout;
                *(unsigned*)(C + (size_t)r0 * CDIM + col) = pack_bf2(v01.x, v01.y);
                *(unsigned*)(C + (size_t)r1 * CDIM + col) = pack_bf2(v23.x, v23.y);
            } else {
                float* C = (float*)Cout;
                if (epi) {
                    float b0v = bias[col], b1v = bias[col + 1];
                    const float* rr0 = residual + (size_t)r0 * CDIM + col;
                    const float* rr1 = residual + (size_t)r1 * CDIM + col;
                    v01.x += b0v + rr0[0]; v01.y += b1v + rr0[1];
                    v23.x += b0v + rr1[0]; v23.y += b1v + rr1[1];
                }
                *(float2*)(C + (size_t)r0 * CDIM + col) = v01;
                *(float2*)(C + (size_t)r1 * CDIM + col) = v23;
            }
        }
    }
}

// ============================================================
// BF16 flash attention (R9 config, best measured).
// ============================================================
__global__ __launch_bounds__(256)
void attn_bf16(const __nv_bfloat16* __restrict__ q,
               const __nv_bfloat16* __restrict__ k,
               const __nv_bfloat16* __restrict__ v,
               __nv_bfloat16* __restrict__ o) {
    extern __shared__ char sm[];
    char* Qs = sm;              // [2 sub][128][80]
    char* Ks = sm + 20480;      // [2 buf][2 sub][64][80]
    char* Vs = sm + 40960;      // [2 buf][2 sub][64][80]

    int qt = blockIdx.x, head = blockIdx.y, b = blockIdx.z;
    int tid = threadIdx.x, warp = tid >> 5, lane = tid & 31;
    int g = lane >> 2, t = lane & 3;

    size_t base = ((size_t)b * S_TOK) * CDIM + head * 64;
    const __nv_bfloat16* qg = q + base;
    const __nv_bfloat16* kg = k + base;
    const __nv_bfloat16* vg = v + base;

    unsigned kbase0 = (unsigned)__cvta_generic_to_shared(Ks);
    unsigned vbase0 = (unsigned)__cvta_generic_to_shared(Vs);

#define KVLOAD(KT, BF)                                                      \
    {                                                                       \
        _Pragma("unroll")                                                   \
        for (int i = 0; i < 2; i++) {                                       \
            int idx = tid + i * 256;                                        \
            int row = idx >> 3, c = idx & 7;                                \
            unsigned off = (BF) * 10240 + (c >> 2) * 5120 + row * 80 + (c & 3) * 16; \
            const __nv_bfloat16* kp = kg + (size_t)((KT) * 64 + row) * CDIM + c * 8; \
            const __nv_bfloat16* vp = vg + (size_t)((KT) * 64 + row) * CDIM + c * 8; \
            CP_ASYNC16(kbase0 + off, kp, 16);                               \
            CP_ASYNC16(vbase0 + off, vp, 16);                               \
        }                                                                   \
        CP_COMMIT();                                                        \
    }

#pragma unroll
    for (int i = 0; i < 4; i++) {
        int idx = tid + i * 256;
        int row = idx >> 3, c = idx & 7;
        uint4 val = *(const uint4*)(qg + (size_t)(qt * 128 + row) * CDIM + c * 8);
        *(uint4*)(Qs + (c >> 2) * 10240 + row * 80 + (c & 3) * 16) = val;
    }
    KVLOAD(0, 0);
    __syncthreads();

    unsigned qf[4][4];
    {
        unsigned qbase = (unsigned)__cvta_generic_to_shared(Qs);
        int arow_f = warp * 16 + (lane & 15);
        int akoff = (lane >> 4) * 8;
        const unsigned sc = 0x3E003E00u;
#pragma unroll
        for (int kst = 0; kst < 4; kst++) {
            unsigned addr = qbase + (kst >> 1) * 10240 +
                            (arow_f * 40 + (kst & 1) * 16 + akoff) * 2;
            LDSM4(qf[kst], addr);
#pragma unroll
            for (int r = 0; r < 4; r++) MULBF2(qf[kst][r], qf[kst][r], sc);
        }
    }

    float o_acc[8][4];
    float mi0 = -1e30f, mi1 = -1e30f, li0 = 0.f, li1 = 0.f;
#pragma unroll
    for (int dj = 0; dj < 8; dj++)
#pragma unroll
        for (int c = 0; c < 4; c++) o_acc[dj][c] = 0.f;

    int brow_f = (lane & 7) + ((lane >> 4) << 3);
    int bkoff  = ((lane >> 3) & 1) * 8;
    int vrow   = (lane & 7) + 8 * ((lane >> 3) & 1);
    int vdo    = (lane >> 4) * 8;

    for (int kt = 0; kt < 16; kt++) {
        int buf = kt & 1;
        __syncthreads();
        if (kt + 1 < 16) KVLOAD(kt + 1, buf ^ 1);
        if (kt + 1 < 16) asm volatile("cp.async.wait_group 1;");
        else             asm volatile("cp.async.wait_group 0;");
        __syncthreads();

        unsigned kb0 = kbase0 + buf * 10240;
        unsigned vb0 = vbase0 + buf * 10240;

        float sv[8][4];
#pragma unroll
        for (int nj = 0; nj < 8; nj++)
#pragma unroll
            for (int c = 0; c < 4; c++) sv[nj][c] = 0.f;

#pragma unroll
        for (int kst = 0; kst < 4; kst++) {
            unsigned kb = kb0 + (kst >> 1) * 5120;
#pragma unroll
            for (int njp = 0; njp < 4; njp++) {
                unsigned bfr[4];
                unsigned addr = kb + ((brow_f + njp * 16) * 40 +
                                      (kst & 1) * 16 + bkoff) * 2;
                LDSM4(bfr, addr);
                MMA_BF16(sv[njp * 2],     qf[kst], bfr[0], bfr[1]);
                MMA_BF16(sv[njp * 2 + 1], qf[kst], bfr[2], bfr[3]);
            }
        }

        float m0 = -1e30f, m1 = -1e30f;
#pragma unroll
        for (int nj = 0; nj < 8; nj++) {
            m0 = fmaxf(m0, fmaxf(sv[nj][0], sv[nj][1]));
            m1 = fmaxf(m1, fmaxf(sv[nj][2], sv[nj][3]));
        }
        m0 = fmaxf(m0, __shfl_xor_sync(0xffffffffu, m0, 1));
        m0 = fmaxf(m0, __shfl_xor_sync(0xffffffffu, m0, 2));
        m1 = fmaxf(m1, __shfl_xor_sync(0xffffffffu, m1, 1));
        m1 = fmaxf(m1, __shfl_xor_sync(0xffffffffu, m1, 2));
        float nm0 = fmaxf(mi0, m0), nm1 = fmaxf(mi1, m1);
        float cr0 = __expf(mi0 - nm0), cr1 = __expf(mi1 - nm1);
        float s0 = 0.f, s1 = 0.f;
#pragma unroll
        for (int nj = 0; nj < 8; nj++) {
            sv[nj][0] = __expf(sv[nj][0] - nm0);
            sv[nj][1] = __expf(sv[nj][1] - nm0);
            sv[nj][2] = __expf(sv[nj][2] - nm1);
            sv[nj][3] = __expf(sv[nj][3] - nm1);
            s0 += sv[nj][0] + sv[nj][1];
            s1 += sv[nj][2] + sv[nj][3];
        }
        s0 += __shfl_xor_sync(0xffffffffu, s0, 1);
        s0 += __shfl_xor_sync(0xffffffffu, s0, 2);
        s1 += __shfl_xor_sync(0xffffffffu, s1, 1);
        s1 += __shfl_xor_sync(0xffffffffu, s1, 2);
        li0 = li0 * cr0 + s0; li1 = li1 * cr1 + s1;
        mi0 = nm0; mi1 = nm1;
#pragma unroll
        for (int dj = 0; dj < 8; dj++) {
            o_acc[dj][0] *= cr0; o_acc[dj][1] *= cr0;
            o_acc[dj][2] *= cr1; o_acc[dj][3] *= cr1;
        }

        unsigned pf[4][4];
#pragma unroll
        for (int j = 0; j < 4; j++) {
            pf[j][0] = pack_bf2(sv[2 * j][0],     sv[2 * j][1]);
            pf[j][1] = pack_bf2(sv[2 * j][2],     sv[2 * j][3]);
            pf[j][2] = pack_bf2(sv[2 * j + 1][0], sv[2 * j + 1][1]);
            pf[j][3] = pack_bf2(sv[2 * j + 1][2], sv[2 * j + 1][3]);
        }

#pragma unroll
        for (int j = 0; j < 4; j++) {
#pragma unroll
            for (int djp = 0; djp < 4; djp++) {
                unsigned bfr[4];
                int d0 = djp * 16;
                unsigned addr = vb0 + (d0 >> 5) * 5120 +
                                ((j * 16 + vrow) * 40 + (d0 & 31) + vdo) * 2;
                LDSM4T(bfr, addr);
                MMA_BF16(o_acc[djp * 2],     pf[j], bfr[0], bfr[1]);
                MMA_BF16(o_acc[djp * 2 + 1], pf[j], bfr[2], bfr[3]);
            }
        }
    }

    float inv0 = 1.f / li0, inv1 = 1.f / li1;
    int gr0 = qt * 128 + warp * 16 + g;
    __nv_bfloat16* or0 = o + ((size_t)b * S_TOK + gr0) * CDIM + head * 64;
    __nv_bfloat16* or1 = or0 + 8 * CDIM;
#pragma unroll
    for (int dj = 0; dj < 8; dj++) {
        *(unsigned*)(or0 + dj * 8 + 2 * t) =
            pack_bf2(o_acc[dj][0] * inv0, o_acc[dj][1] * inv0);
        *(unsigned*)(or1 + dj * 8 + 2 * t) =
            pack_bf2(o_acc[dj][2] * inv1, o_acc[dj][3] * inv1);
    }
}

// ============================================================
// launch
// ============================================================
extern "C" void kernel_launch(void* const* d_in, const int* in_sizes, int n_in,
                              void* d_out, int out_size) {
    const float* x       = (const float*)d_in[0];
    const float* gamma   = (const float*)d_in[1];
    const float* beta    = (const float*)d_in[2];
    const float* wq      = (const float*)d_in[3];
    const float* wk      = (const float*)d_in[4];
    const float* wv      = (const float*)d_in[5];
    const float* conv_w  = (const float*)d_in[6];
    const float* conv_b  = (const float*)d_in[7];
    float* out = (float*)d_out;

    __nv_bfloat16 *xnh, *abh, *wt, *qh, *kh, *vh;
    cudaGetSymbolAddress((void**)&xnh, g_xn_h);
    cudaGetSymbolAddress((void**)&abh, g_attn_h);
    cudaGetSymbolAddress((void**)&wt,  g_wt);
    cudaGetSymbolAddress((void**)&qh, g_qh);
    cudaGetSymbolAddress((void**)&kh, g_kh);
    cudaGetSymbolAddress((void**)&vh, g_vh);

    const int gemm_smem = 3 * STG_BYTES;      // 61440
    const int attn_smem = 61440;
    cudaFuncSetAttribute(gemm_bf16, cudaFuncAttributeMaxDynamicSharedMemorySize, gemm_smem);
    cudaFuncSetAttribute(attn_bf16, cudaFuncAttributeMaxDynamicSharedMemorySize, attn_smem);

    // GroupNorm: stats + apply (bf16 out); weight transpose/convert
    gn_stats<<<128, 256>>>(x);
    wt_kernel<<<dim3(16, 16, 12), dim3(32, 8)>>>(wq, wk, wv, conv_w, wt);
    gn_apply<<<512, 256>>>(x, gamma, beta, xnh);

    // QKV projections: ONE fused launch (z = q/k/v) to kill wave tails
    gemm_bf16<<<dim3(4, 128, 3), 256, gemm_smem>>>(
        xnh, wt, qh, kh, vh, 1, 1, nullptr, nullptr, 0);

    // Attention (bf16 tensor cores, async K/V pipeline)
    attn_bf16<<<dim3(8, 8, 16), 256, attn_smem>>>(qh, kh, vh, abh);

    // 3x3 conv: fused 9-tap bf16 GEMM, fp32 out with bias + residual
    gemm_bf16<<<dim3(4, 128, 1), 256, gemm_smem>>>(
        abh, wt + 3 * (size_t)CDIM * CDIM, out, out, out, 9, 0, conv_b, x, 1);
}

// round 16
// speedup vs baseline: 1.5001x; 1.5001x over previous
#include <cuda_runtime.h>
#include <cuda_bf16.h>
#include <stdint.h>
#include <math.h>

#define S_TOK 1024
#define CDIM  512
#define NTOK  16384   // B * S_TOK

// ---- scratch (static device globals; no runtime allocation) ----
__device__ __nv_bfloat16 g_xn_h  [NTOK * CDIM];
__device__ __nv_bfloat16 g_attn_h[NTOK * CDIM];
__device__ __nv_bfloat16 g_wt    [12 * CDIM * CDIM];  // [z][n][k] bf16
__device__ __nv_bfloat16 g_qh[NTOK * CDIM];
__device__ __nv_bfloat16 g_kh[NTOK * CDIM];
__device__ __nv_bfloat16 g_vh[NTOK * CDIM];

// ============================================================
// GroupNorm -> bf16 output
// ============================================================
__global__ void gn_kernel(const float* __restrict__ x,
                          const float* __restrict__ gamma,
                          const float* __restrict__ beta,
                          __nv_bfloat16* __restrict__ xn) {
    int bg = blockIdx.x;
    int b = bg >> 5, g = bg & 31;
    const float* xb = x + (size_t)b * S_TOK * CDIM + g * 16;
    __nv_bfloat16* xo = xn + (size_t)b * S_TOK * CDIM + g * 16;

    float sum = 0.f, sumsq = 0.f;
    for (int task = threadIdx.x; task < 4096; task += 256) {
        int s = task >> 2, c4 = (task & 3) * 4;
        float4 v = *(const float4*)(xb + s * CDIM + c4);
        sum += v.x + v.y + v.z + v.w;
        sumsq += v.x * v.x + v.y * v.y + v.z * v.z + v.w * v.w;
    }
    __shared__ float red[256], red2[256];
    red[threadIdx.x] = sum; red2[threadIdx.x] = sumsq;
    __syncthreads();
    for (int off = 128; off > 0; off >>= 1) {
        if (threadIdx.x < off) {
            red[threadIdx.x]  += red[threadIdx.x + off];
            red2[threadIdx.x] += red2[threadIdx.x + off];
        }
        __syncthreads();
    }
    float mean = red[0] * (1.f / 16384.f);
    float var  = red2[0] * (1.f / 16384.f) - mean * mean;
    float inv  = rsqrtf(var + 1e-5f);

    for (int task = threadIdx.x; task < 4096; task += 256) {
        int s = task >> 2, c4 = (task & 3) * 4;
        float4 v = *(const float4*)(xb + s * CDIM + c4);
        float4 ga = *(const float4*)(gamma + g * 16 + c4);
        float4 be = *(const float4*)(beta  + g * 16 + c4);
        float o0 = (v.x - mean) * inv * ga.x + be.x;
        float o1 = (v.y - mean) * inv * ga.y + be.y;
        float o2 = (v.z - mean) * inv * ga.z + be.z;
        float o3 = (v.w - mean) * inv * ga.w + be.w;
        __nv_bfloat162 p0 = __floats2bfloat162_rn(o0, o1);
        __nv_bfloat162 p1 = __floats2bfloat162_rn(o2, o3);
        uint2 pk = make_uint2(*(unsigned*)&p0, *(unsigned*)&p1);
        *(uint2*)(xo + s * CDIM + c4) = pk;
    }
}

// ============================================================
// Weight transpose + convert: out[z][n][k] = bf16(src_z[k][n])
// ============================================================
__global__ void wt_kernel(const float* __restrict__ wq, const float* __restrict__ wk,
                          const float* __restrict__ wv, const float* __restrict__ cw,
                          __nv_bfloat16* __restrict__ out) {
    __shared__ float tile[32][33];
    int z = blockIdx.z;
    const float* src = (z == 0) ? wq : (z == 1) ? wk : (z == 2) ? wv
                       : cw + (size_t)(z - 3) * CDIM * CDIM;
    __nv_bfloat16* dst = out + (size_t)z * CDIM * CDIM;
    int k0 = blockIdx.y * 32, n0 = blockIdx.x * 32;
    int tx = threadIdx.x, ty = threadIdx.y;
#pragma unroll
    for (int i = 0; i < 32; i += 8)
        tile[ty + i][tx] = src[(size_t)(k0 + ty + i) * CDIM + n0 + tx];
    __syncthreads();
#pragma unroll
    for (int i = 0; i < 32; i += 8)
        dst[(size_t)(n0 + ty + i) * CDIM + k0 + tx] = __float2bfloat16(tile[tx][ty + i]);
}

// ============================================================
// mma / ldmatrix / cp.async helpers
// ============================================================
#define MMA_BF16(d, a, b0, b1)                                              \
    asm volatile(                                                           \
        "mma.sync.aligned.m16n8k16.row.col.f32.bf16.bf16.f32 "              \
        "{%0,%1,%2,%3}, {%4,%5,%6,%7}, {%8,%9}, {%0,%1,%2,%3};\n"           \
        : "+f"(d[0]), "+f"(d[1]), "+f"(d[2]), "+f"(d[3])                    \
        : "r"(a[0]), "r"(a[1]), "r"(a[2]), "r"(a[3]), "r"(b0), "r"(b1))

#define LDSM4(r, addr)                                                      \
    asm volatile("ldmatrix.sync.aligned.m8n8.x4.shared.b16 {%0,%1,%2,%3}, [%4];\n" \
                 : "=r"(r[0]), "=r"(r[1]), "=r"(r[2]), "=r"(r[3]) : "r"(addr))

#define LDSM4T(r, addr)                                                     \
    asm volatile("ldmatrix.sync.aligned.m8n8.x4.trans.shared.b16 {%0,%1,%2,%3}, [%4];\n" \
                 : "=r"(r[0]), "=r"(r[1]), "=r"(r[2]), "=r"(r[3]) : "r"(addr))

#define CP_ASYNC16(daddr, gptr, sz)                                         \
    asm volatile("cp.async.cg.shared.global [%0], [%1], 16, %2;\n"          \
                 :: "r"(daddr), "l"(gptr), "r"(sz))
#define CP_COMMIT() asm volatile("cp.async.commit_group;\n")

#define MULBF2(dst, a, b)                                                   \
    asm volatile("mul.rn.bf16x2 %0, %1, %2;\n" : "=r"(dst) : "r"(a), "r"(b))

__device__ __forceinline__ unsigned pack_bf2(float a, float b) {
    __nv_bfloat162 h = __floats2bfloat162_rn(a, b);
    return *(unsigned*)&h;
}

// ============================================================
// BF16 GEMM (R7 config, best measured): 8 warps, 64x32 warp
// tiles, CTA 128x128, BK=32, 3-stage cp.async ring, 80B stride.
//   C[16384,512] = sum_tap Ashift[16384,512] @ Wt_tap^T
// ============================================================
#define STG_BYTES 20480   // per stage: A 128*80 + B 128*80

__global__ __launch_bounds__(256)
void gemm_bf16(const __nv_bfloat16* __restrict__ A,
               const __nv_bfloat16* __restrict__ Wt,
               void* __restrict__ Cout, int ntaps, int obf,
               const float* __restrict__ bias,
               const float* __restrict__ residual, int epi) {
    extern __shared__ char smem[];

    int tid = threadIdx.x, warp = tid >> 5, lane = tid & 31;
    int g = lane >> 2, t = lane & 3;
    int m0 = blockIdx.y * 128, n0 = blockIdx.x * 128;
    int wm = (warp >> 2) * 64, wn = (warp & 3) * 32;

    int lrow = tid >> 2, lchunk = tid & 3;
    int bidx[2], hh0[2], ww0[2];
#pragma unroll
    for (int p = 0; p < 2; p++) {
        int mg = m0 + lrow + 64 * p;
        bidx[p] = mg >> 10;
        int s = mg & 1023;
        hh0[p] = s >> 5; ww0[p] = s & 31;
    }

    float acc[4][4][4];
#pragma unroll
    for (int mi = 0; mi < 4; mi++)
#pragma unroll
        for (int nj = 0; nj < 4; nj++)
#pragma unroll
            for (int c = 0; c < 4; c++) acc[mi][nj][c] = 0.f;

    const int NIT = ntaps * 16;

#define LOAD_TILE(IT, ST)                                                   \
    {                                                                       \
        int tap = (IT) >> 4;                                                \
        int k0 = ((IT) & 15) << 5;                                          \
        int dh = 0, dw = 0;                                                 \
        if (ntaps > 1) { int r3 = tap / 3; dh = r3 - 1; dw = tap - r3 * 3 - 1; } \
        char* as = smem + (ST) * STG_BYTES;                                 \
        char* bs = as + 10240;                                              \
        _Pragma("unroll")                                                   \
        for (int p = 0; p < 2; p++) {                                       \
            int hh = hh0[p] + dh, ww = ww0[p] + dw;                         \
            bool valid = ((unsigned)hh < 32u) && ((unsigned)ww < 32u);      \
            const __nv_bfloat16* gp = A + (size_t)((bidx[p] << 10) + (hh << 5) + ww) * CDIM + k0 + lchunk * 8; \
            unsigned da = (unsigned)__cvta_generic_to_shared(as + (lrow + 64 * p) * 80 + lchunk * 16); \
            CP_ASYNC16(da, gp, valid ? 16 : 0);                             \
        }                                                                   \
        const __nv_bfloat16* wb = Wt + (size_t)tap * CDIM * CDIM + (size_t)n0 * CDIM + k0; \
        _Pragma("unroll")                                                   \
        for (int p = 0; p < 2; p++) {                                       \
            const __nv_bfloat16* gp = wb + (size_t)(lrow + 64 * p) * CDIM + lchunk * 8; \
            unsigned da = (unsigned)__cvta_generic_to_shared(bs + (lrow + 64 * p) * 80 + lchunk * 16); \
            CP_ASYNC16(da, gp, 16);                                         \
        }                                                                   \
        CP_COMMIT();                                                        \
    }

    LOAD_TILE(0, 0);
    LOAD_TILE(1, 1);

    int arow_f = wm + (lane & 15);
    int akoff  = (lane >> 4) * 8;
    int brow_f = wn + (lane & 7) + ((lane >> 4) << 3);
    int bkoff  = ((lane >> 3) & 1) * 8;

    int st = 0;
    for (int it = 0; it < NIT; it++) {
        if (it + 1 < NIT) asm volatile("cp.async.wait_group 1;");
        else              asm volatile("cp.async.wait_group 0;");
        __syncthreads();
        // stage (it+2)%3 was last read at it-1; free after this barrier.
        if (it + 2 < NIT) {
            int wst = st + 2; if (wst >= 3) wst -= 3;
            LOAD_TILE(it + 2, wst);
        }
        char* as = smem + st * STG_BYTES;
        char* bs = as + 10240;
        unsigned abase = (unsigned)__cvta_generic_to_shared(as);
        unsigned bbase = (unsigned)__cvta_generic_to_shared(bs);

#pragma unroll
        for (int ks = 0; ks < 2; ks++) {
            unsigned bfr[2][4];
#pragma unroll
            for (int njp = 0; njp < 2; njp++) {
                unsigned addr = bbase + ((brow_f + njp * 16) * 40 + ks * 16 + bkoff) * 2;
                LDSM4(bfr[njp], addr);
            }
#pragma unroll
            for (int mi = 0; mi < 4; mi++) {
                unsigned af[4];
                unsigned addr = abase + ((arow_f + mi * 16) * 40 + ks * 16 + akoff) * 2;
                LDSM4(af, addr);
                MMA_BF16(acc[mi][0], af, bfr[0][0], bfr[0][1]);
                MMA_BF16(acc[mi][1], af, bfr[0][2], bfr[0][3]);
                MMA_BF16(acc[mi][2], af, bfr[1][0], bfr[1][1]);
                MMA_BF16(acc[mi][3], af, bfr[1][2], bfr[1][3]);
            }
        }
        st++; if (st == 3) st = 0;
    }

    // epilogue
#pragma unroll
    for (int mi = 0; mi < 4; mi++) {
        int r0 = m0 + wm + mi * 16 + g;
        int r1 = r0 + 8;
#pragma unroll
        for (int nj = 0; nj < 4; nj++) {
            int col = n0 + wn + nj * 8 + 2 * t;
            float2 v01 = make_float2(acc[mi][nj][0], acc[mi][nj][1]);
            float2 v23 = make_float2(acc[mi][nj][2], acc[mi][nj][3]);
            if (obf) {
                __nv_bfloat16* C = (__nv_bfloat16*)Cout;
                *(unsigned*)(C + (size_t)r0 * CDIM + col) = pack_bf2(v01.x, v01.y);
                *(unsigned*)(C + (size_t)r1 * CDIM + col) = pack_bf2(v23.x, v23.y);
            } else {
                float* C = (float*)Cout;
                if (epi) {
                    float b0v = bias[col], b1v = bias[col + 1];
                    const float* rr0 = residual + (size_t)r0 * CDIM + col;
                    const float* rr1 = residual + (size_t)r1 * CDIM + col;
                    v01.x += b0v + rr0[0]; v01.y += b1v + rr0[1];
                    v23.x += b0v + rr1[0]; v23.y += b1v + rr1[1];
                }
                *(float2*)(C + (size_t)r0 * CDIM + col) = v01;
                *(float2*)(C + (size_t)r1 * CDIM + col) = v23;
            }
        }
    }
}

// ============================================================
// BF16 flash attention, cp.async double-buffered K/V (R9 config,
// best measured). Softmax 1/8 scale folded into Q frags.
// Smem: Q 20480 + K 2x10240 + V 2x10240 = 61440 B.
// ============================================================
__global__ __launch_bounds__(256)
void attn_bf16(const __nv_bfloat16* __restrict__ q,
               const __nv_bfloat16* __restrict__ k,
               const __nv_bfloat16* __restrict__ v,
               __nv_bfloat16* __restrict__ o) {
    extern __shared__ char sm[];
    char* Qs = sm;              // [2 sub][128][80]
    char* Ks = sm + 20480;      // [2 buf][2 sub][64][80]
    char* Vs = sm + 40960;      // [2 buf][2 sub][64][80]

    int qt = blockIdx.x, head = blockIdx.y, b = blockIdx.z;
    int tid = threadIdx.x, warp = tid >> 5, lane = tid & 31;
    int g = lane >> 2, t = lane & 3;

    size_t base = ((size_t)b * S_TOK) * CDIM + head * 64;
    const __nv_bfloat16* qg = q + base;
    const __nv_bfloat16* kg = k + base;
    const __nv_bfloat16* vg = v + base;

    unsigned kbase0 = (unsigned)__cvta_generic_to_shared(Ks);
    unsigned vbase0 = (unsigned)__cvta_generic_to_shared(Vs);

#define KVLOAD(KT, BF)                                                      \
    {                                                                       \
        _Pragma("unroll")                                                   \
        for (int i = 0; i < 2; i++) {                                       \
            int idx = tid + i * 256;                                        \
            int row = idx >> 3, c = idx & 7;                                \
            unsigned off = (BF) * 10240 + (c >> 2) * 5120 + row * 80 + (c & 3) * 16; \
            const __nv_bfloat16* kp = kg + (size_t)((KT) * 64 + row) * CDIM + c * 8; \
            const __nv_bfloat16* vp = vg + (size_t)((KT) * 64 + row) * CDIM + c * 8; \
            CP_ASYNC16(kbase0 + off, kp, 16);                               \
            CP_ASYNC16(vbase0 + off, vp, 16);                               \
        }                                                                   \
        CP_COMMIT();                                                        \
    }

    // load Q tile [128 x 64]
#pragma unroll
    for (int i = 0; i < 4; i++) {
        int idx = tid + i * 256;
        int row = idx >> 3, c = idx & 7;
        uint4 val = *(const uint4*)(qg + (size_t)(qt * 128 + row) * CDIM + c * 8);
        *(uint4*)(Qs + (c >> 2) * 10240 + row * 80 + (c & 3) * 16) = val;
    }
    KVLOAD(0, 0);
    __syncthreads();

    // hoist Q frags, fold in 1/8 scale (bf16 0.125 exact)
    unsigned qf[4][4];
    {
        unsigned qbase = (unsigned)__cvta_generic_to_shared(Qs);
        int arow_f = warp * 16 + (lane & 15);
        int akoff = (lane >> 4) * 8;
        const unsigned sc = 0x3E003E00u;
#pragma unroll
        for (int kst = 0; kst < 4; kst++) {
            unsigned addr = qbase + (kst >> 1) * 10240 +
                            (arow_f * 40 + (kst & 1) * 16 + akoff) * 2;
            LDSM4(qf[kst], addr);
#pragma unroll
            for (int r = 0; r < 4; r++) MULBF2(qf[kst][r], qf[kst][r], sc);
        }
    }

    float o_acc[8][4];
    float mi0 = -1e30f, mi1 = -1e30f, li0 = 0.f, li1 = 0.f;
#pragma unroll
    for (int dj = 0; dj < 8; dj++)
#pragma unroll
        for (int c = 0; c < 4; c++) o_acc[dj][c] = 0.f;

    int brow_f = (lane & 7) + ((lane >> 4) << 3);
    int bkoff  = ((lane >> 3) & 1) * 8;
    int vrow   = (lane & 7) + 8 * ((lane >> 3) & 1);
    int vdo    = (lane >> 4) * 8;

    for (int kt = 0; kt < 16; kt++) {
        int buf = kt & 1;
        __syncthreads();
        if (kt + 1 < 16) KVLOAD(kt + 1, buf ^ 1);
        if (kt + 1 < 16) asm volatile("cp.async.wait_group 1;");
        else             asm volatile("cp.async.wait_group 0;");
        __syncthreads();

        unsigned kb0 = kbase0 + buf * 10240;
        unsigned vb0 = vbase0 + buf * 10240;

        float sv[8][4];
#pragma unroll
        for (int nj = 0; nj < 8; nj++)
#pragma unroll
            for (int c = 0; c < 4; c++) sv[nj][c] = 0.f;

#pragma unroll
        for (int kst = 0; kst < 4; kst++) {
            unsigned kb = kb0 + (kst >> 1) * 5120;
#pragma unroll
            for (int njp = 0; njp < 4; njp++) {
                unsigned bfr[4];
                unsigned addr = kb + ((brow_f + njp * 16) * 40 +
                                      (kst & 1) * 16 + bkoff) * 2;
                LDSM4(bfr, addr);
                MMA_BF16(sv[njp * 2],     qf[kst], bfr[0], bfr[1]);
                MMA_BF16(sv[njp * 2 + 1], qf[kst], bfr[2], bfr[3]);
            }
        }

        float m0 = -1e30f, m1 = -1e30f;
#pragma unroll
        for (int nj = 0; nj < 8; nj++) {
            m0 = fmaxf(m0, fmaxf(sv[nj][0], sv[nj][1]));
            m1 = fmaxf(m1, fmaxf(sv[nj][2], sv[nj][3]));
        }
        m0 = fmaxf(m0, __shfl_xor_sync(0xffffffffu, m0, 1));
        m0 = fmaxf(m0, __shfl_xor_sync(0xffffffffu, m0, 2));
        m1 = fmaxf(m1, __shfl_xor_sync(0xffffffffu, m1, 1));
        m1 = fmaxf(m1, __shfl_xor_sync(0xffffffffu, m1, 2));
        float nm0 = fmaxf(mi0, m0), nm1 = fmaxf(mi1, m1);
        float cr0 = __expf(mi0 - nm0), cr1 = __expf(mi1 - nm1);
        float s0 = 0.f, s1 = 0.f;
#pragma unroll
        for (int nj = 0; nj < 8; nj++) {
            sv[nj][0] = __expf(sv[nj][0] - nm0);
            sv[nj][1] = __expf(sv[nj][1] - nm0);
            sv[nj][2] = __expf(sv[nj][2] - nm1);
            sv[nj][3] = __expf(sv[nj][3] - nm1);
            s0 += sv[nj][0] + sv[nj][1];
            s1 += sv[nj][2] + sv[nj][3];
        }
        s0 += __shfl_xor_sync(0xffffffffu, s0, 1);
        s0 += __shfl_xor_sync(0xffffffffu, s0, 2);
        s1 += __shfl_xor_sync(0xffffffffu, s1, 1);
        s1 += __shfl_xor_sync(0xffffffffu, s1, 2);
        li0 = li0 * cr0 + s0; li1 = li1 * cr1 + s1;
        mi0 = nm0; mi1 = nm1;
#pragma unroll
        for (int dj = 0; dj < 8; dj++) {
            o_acc[dj][0] *= cr0; o_acc[dj][1] *= cr0;
            o_acc[dj][2] *= cr1; o_acc[dj][3] *= cr1;
        }

        unsigned pf[4][4];
#pragma unroll
        for (int j = 0; j < 4; j++) {
            pf[j][0] = pack_bf2(sv[2 * j][0],     sv[2 * j][1]);
            pf[j][1] = pack_bf2(sv[2 * j][2],     sv[2 * j][3]);
            pf[j][2] = pack_bf2(sv[2 * j + 1][0], sv[2 * j + 1][1]);
            pf[j][3] = pack_bf2(sv[2 * j + 1][2], sv[2 * j + 1][3]);
        }

#pragma unroll
        for (int j = 0; j < 4; j++) {
#pragma unroll
            for (int djp = 0; djp < 4; djp++) {
                unsigned bfr[4];
                int d0 = djp * 16;
                unsigned addr = vb0 + (d0 >> 5) * 5120 +
                                ((j * 16 + vrow) * 40 + (d0 & 31) + vdo) * 2;
                LDSM4T(bfr, addr);
                MMA_BF16(o_acc[djp * 2],     pf[j], bfr[0], bfr[1]);
                MMA_BF16(o_acc[djp * 2 + 1], pf[j], bfr[2], bfr[3]);
            }
        }
    }

    float inv0 = 1.f / li0, inv1 = 1.f / li1;
    int gr0 = qt * 128 + warp * 16 + g;
    __nv_bfloat16* or0 = o + ((size_t)b * S_TOK + gr0) * CDIM + head * 64;
    __nv_bfloat16* or1 = or0 + 8 * CDIM;
#pragma unroll
    for (int dj = 0; dj < 8; dj++) {
        *(unsigned*)(or0 + dj * 8 + 2 * t) =
            pack_bf2(o_acc[dj][0] * inv0, o_acc[dj][1] * inv0);
        *(unsigned*)(or1 + dj * 8 + 2 * t) =
            pack_bf2(o_acc[dj][2] * inv1, o_acc[dj][3] * inv1);
    }
}

// ============================================================
// launch
// ============================================================
extern "C" void kernel_launch(void* const* d_in, const int* in_sizes, int n_in,
                              void* d_out, int out_size) {
    const float* x       = (const float*)d_in[0];
    const float* gamma   = (const float*)d_in[1];
    const float* beta    = (const float*)d_in[2];
    const float* wq      = (const float*)d_in[3];
    const float* wk      = (const float*)d_in[4];
    const float* wv      = (const float*)d_in[5];
    const float* conv_w  = (const float*)d_in[6];
    const float* conv_b  = (const float*)d_in[7];
    float* out = (float*)d_out;

    __nv_bfloat16 *xnh, *abh, *wt, *qh, *kh, *vh;
    cudaGetSymbolAddress((void**)&xnh, g_xn_h);
    cudaGetSymbolAddress((void**)&abh, g_attn_h);
    cudaGetSymbolAddress((void**)&wt,  g_wt);
    cudaGetSymbolAddress((void**)&qh, g_qh);
    cudaGetSymbolAddress((void**)&kh, g_kh);
    cudaGetSymbolAddress((void**)&vh, g_vh);

    const int gemm_smem = 3 * STG_BYTES;      // 61440
    const int attn_smem = 61440;
    cudaFuncSetAttribute(gemm_bf16, cudaFuncAttributeMaxDynamicSharedMemorySize, gemm_smem);
    cudaFuncSetAttribute(attn_bf16, cudaFuncAttributeMaxDynamicSharedMemorySize, attn_smem);

    // GroupNorm (bf16 out) + weight transpose/convert
    gn_kernel<<<512, 256>>>(x, gamma, beta, xnh);
    wt_kernel<<<dim3(16, 16, 12), dim3(32, 8)>>>(wq, wk, wv, conv_w, wt);

    // QKV projections (bf16 in/out) — three specialized launches
    dim3 ggrid(CDIM / 128, NTOK / 128);
    gemm_bf16<<<ggrid, 256, gemm_smem>>>(xnh, wt + 0 * (size_t)CDIM * CDIM, qh, 1, 1, nullptr, nullptr, 0);
    gemm_bf16<<<ggrid, 256, gemm_smem>>>(xnh, wt + 1 * (size_t)CDIM * CDIM, kh, 1, 1, nullptr, nullptr, 0);
    gemm_bf16<<<ggrid, 256, gemm_smem>>>(xnh, wt + 2 * (size_t)CDIM * CDIM, vh, 1, 1, nullptr, nullptr, 0);

    // Attention (bf16 tensor cores, async K/V pipeline)
    attn_bf16<<<dim3(8, 8, 16), 256, attn_smem>>>(qh, kh, vh, abh);

    // 3x3 conv: fused 9-tap bf16 GEMM, fp32 out with bias + residual
    gemm_bf16<<<ggrid, 256, gemm_smem>>>(abh, wt + 3 * (size_t)CDIM * CDIM, out, 9, 0, conv_b, x, 1);
}